// round 2
// baseline (speedup 1.0000x reference)
#include <cuda_runtime.h>

#define BB 4
#define SS 1024
#define HIDD 1024
#define HH 16
#define DD 64
#define MAXP 1024

// Scratch for Q,K,V projections: [B,S,H*D] row-major (matches heads() reshape)
__device__ float g_q[BB*SS*HIDD];
__device__ float g_k[BB*SS*HIDD];
__device__ float g_v[BB*SS*HIDD];

// ---------------------------------------------------------------------------
// QKV GEMM: C[4096,1024] = X[4096,1024] @ W[1024,1024] + bias
// 128x128 tile, BK=16, 256 threads, 8x8 micro-tile (split 4+4 columns/rows
// for conflict-free vectorized LDS).
// blockIdx.z selects {Wq,Wk,Wv}.
// ---------------------------------------------------------------------------
#define GT 128
#define GK 16

__global__ __launch_bounds__(256) void qkv_gemm(
    const float* __restrict__ X,
    const float* __restrict__ Wq, const float* __restrict__ bq,
    const float* __restrict__ Wk, const float* __restrict__ bk,
    const float* __restrict__ Wv, const float* __restrict__ bv)
{
    const float* Wm; const float* bias; float* out;
    if (blockIdx.z == 0)      { Wm = Wq; bias = bq; out = g_q; }
    else if (blockIdx.z == 1) { Wm = Wk; bias = bk; out = g_k; }
    else                      { Wm = Wv; bias = bv; out = g_v; }

    __shared__ float As[GK][GT + 1];   // [kk][m], stride 129 -> conflict-free transpose store
    __shared__ float Bs[GK][GT];       // [kk][n]

    const int tid = threadIdx.x;
    const int tx = tid & 15, ty = tid >> 4;
    const int m0 = blockIdx.y * GT, n0 = blockIdx.x * GT;

    float acc[8][8];
    #pragma unroll
    for (int i = 0; i < 8; i++)
        #pragma unroll
        for (int j = 0; j < 8; j++) acc[i][j] = 0.f;

    for (int k0 = 0; k0 < HIDD; k0 += GK) {
        // A tile: 128 rows x 16 k. Each thread loads one float4 along k,
        // stores transposed (scalar) into As[kk][m].
        {
            // 128*16/4 = 512 float4 loads; 256 threads -> 2 each
            #pragma unroll
            for (int r = 0; r < 2; r++) {
                int idx = tid + r * 256;          // 0..511
                int m = idx >> 2, k4 = (idx & 3) * 4;
                float4 v = *reinterpret_cast<const float4*>(
                    &X[(size_t)(m0 + m) * HIDD + k0 + k4]);
                As[k4 + 0][m] = v.x;
                As[k4 + 1][m] = v.y;
                As[k4 + 2][m] = v.z;
                As[k4 + 3][m] = v.w;
            }
        }
        // B tile: 16 k-rows x 128 n, contiguous along n -> float4 direct
        {
            #pragma unroll
            for (int r = 0; r < 2; r++) {
                int idx = tid + r * 256;          // 0..511
                int kk = idx >> 5, n4 = (idx & 31) * 4;
                float4 v = *reinterpret_cast<const float4*>(
                    &Wm[(size_t)(k0 + kk) * HIDD + n0 + n4]);
                *reinterpret_cast<float4*>(&Bs[kk][n4]) = v;
            }
        }
        __syncthreads();

        #pragma unroll
        for (int kk = 0; kk < GK; kk++) {
            float a[8], bf[8];
            #pragma unroll
            for (int i = 0; i < 4; i++) {
                a[i]     = As[kk][ty * 4 + i];
                a[i + 4] = As[kk][64 + ty * 4 + i];
            }
            #pragma unroll
            for (int j = 0; j < 4; j++) {
                bf[j]     = Bs[kk][tx * 4 + j];
                bf[j + 4] = Bs[kk][64 + tx * 4 + j];
            }
            #pragma unroll
            for (int i = 0; i < 8; i++)
                #pragma unroll
                for (int j = 0; j < 8; j++)
                    acc[i][j] += a[i] * bf[j];
        }
        __syncthreads();
    }

    #pragma unroll
    for (int i = 0; i < 8; i++) {
        int m = m0 + ((i < 4) ? (ty * 4 + i) : (64 + ty * 4 + (i - 4)));
        #pragma unroll
        for (int j = 0; j < 8; j++) {
            int n = n0 + ((j < 4) ? (tx * 4 + j) : (64 + tx * 4 + (j - 4)));
            out[(size_t)m * HIDD + n] = acc[i][j] + bias[n];
        }
    }
}

// ---------------------------------------------------------------------------
// Fused attention: per (b, h, 64-query block):
//   S = Q@K^T + Q@E^T(band)  -> /8 + attn_mask -> exp -> *skim
//   accumulate O += P@V and rowsum; normalize by 1/(eps+rowsum) at end.
// Single pass (no max subtraction in the reference softmax).
// ---------------------------------------------------------------------------
#define BM 64
#define BN 64

// smem layout (floats):
//  Qs 64*65 | Ks 64*65 | Es 128*65 | Ps 64*65 | Vs 64*64 | Ms 64 | Sk 64 | RS 64*17 | Rsum 64
#define SMEM_FLOATS (64*65 + 64*65 + 128*65 + 64*65 + 64*64 + 64 + 64 + 64*17 + 64)

__global__ __launch_bounds__(256) void attn_kernel(
    const float* __restrict__ amask,   // [B,1,1,S] -> [B,S]
    const int*   __restrict__ skim,    // [B,S]
    const float* __restrict__ dist,    // [2*MAXP-1, D]
    float*       __restrict__ out)     // [B,S,HID]
{
    extern __shared__ float smf[];
    float* Qs   = smf;
    float* Ks   = Qs + 64 * 65;
    float* Es   = Ks + 64 * 65;
    float* Ps   = Es + 128 * 65;
    float* Vs   = Ps + 64 * 65;
    float* Ms   = Vs + 64 * 64;
    float* Sk   = Ms + 64;
    float* RS   = Sk + 64;
    float* Rsum = RS + 64 * 17;

    const int l0 = blockIdx.x * BM;
    const int h  = blockIdx.y;
    const int b  = blockIdx.z;
    const int tid = threadIdx.x;
    const int tx = tid & 15, ty = tid >> 4;

    const float* Qg = g_q + (size_t)b * SS * HIDD + h * DD;
    const float* Kg = g_k + (size_t)b * SS * HIDD + h * DD;
    const float* Vg = g_v + (size_t)b * SS * HIDD + h * DD;

    // load Q tile [64,64] via float4 (rows 16B-aligned: h*DD multiple of 64)
    #pragma unroll
    for (int r = 0; r < 4; r++) {
        int idx = tid + r * 256;          // 0..1023 float4s
        int li = idx >> 4, d4 = (idx & 15) * 4;
        float4 v = *reinterpret_cast<const float4*>(
            &Qg[(size_t)(l0 + li) * HIDD + d4]);
        float* q = &Qs[li * 65 + d4];
        q[0] = v.x; q[1] = v.y; q[2] = v.z; q[3] = v.w;
    }

    float acc_o[4][4];
    float rs[4];
    #pragma unroll
    for (int i = 0; i < 4; i++) {
        rs[i] = 0.f;
        #pragma unroll
        for (int j = 0; j < 4; j++) acc_o[i][j] = 0.f;
    }

    const int e0 = ty * 4 - tx * 4 + 63;   // e = li-ri+63 = e0 + (i-j), in [0,126]

    for (int r0 = 0; r0 < SS; r0 += BN) {
        __syncthreads();   // previous iteration's Ks/Vs reads done

        // K and V tiles [64,64] via float4
        #pragma unroll
        for (int r = 0; r < 4; r++) {
            int idx = tid + r * 256;
            int ri = idx >> 4, d4 = (idx & 15) * 4;
            float4 kv = *reinterpret_cast<const float4*>(
                &Kg[(size_t)(r0 + ri) * HIDD + d4]);
            float* ks = &Ks[ri * 65 + d4];
            ks[0] = kv.x; ks[1] = kv.y; ks[2] = kv.z; ks[3] = kv.w;
            float4 vv = *reinterpret_cast<const float4*>(
                &Vg[(size_t)(r0 + ri) * HIDD + d4]);
            *reinterpret_cast<float4*>(&Vs[ri * 64 + d4]) = vv;
        }
        // dist_emb band: rows base+e, e in [0,127]; only e<=126 used.
        // dist rows are 64 floats = 256B aligned -> float4 safe.
        int base = l0 - r0 + MAXP - 1 - 63;   // l0 - r0 + 960, in [0,1920]
        #pragma unroll
        for (int r = 0; r < 8; r++) {
            int idx = tid + r * 256;          // 0..2047 float4s
            int e = idx >> 4, d4 = (idx & 15) * 4;
            int g = base + e;
            float4 v;
            if (g < 2 * MAXP - 1)
                v = *reinterpret_cast<const float4*>(&dist[(size_t)g * DD + d4]);
            else
                v = make_float4(0.f, 0.f, 0.f, 0.f);
            float* es = &Es[e * 65 + d4];
            es[0] = v.x; es[1] = v.y; es[2] = v.z; es[3] = v.w;
        }
        if (tid < 64) {
            Ms[tid] = amask[b * SS + r0 + tid];
            Sk[tid] = (float)skim[b * SS + r0 + tid];
        }
        __syncthreads();

        // scores = Q@K^T + Q@E^T
        float acc[4][4];
        #pragma unroll
        for (int i = 0; i < 4; i++)
            #pragma unroll
            for (int j = 0; j < 4; j++) acc[i][j] = 0.f;

        #pragma unroll 2
        for (int d = 0; d < DD; d++) {
            float qv[4], kv[4], ev[7];
            #pragma unroll
            for (int i = 0; i < 4; i++) qv[i] = Qs[(ty * 4 + i) * 65 + d];
            #pragma unroll
            for (int j = 0; j < 4; j++) kv[j] = Ks[(tx * 4 + j) * 65 + d];
            #pragma unroll
            for (int t = 0; t < 7; t++) ev[t] = Es[(e0 - 3 + t) * 65 + d];
            #pragma unroll
            for (int i = 0; i < 4; i++)
                #pragma unroll
                for (int j = 0; j < 4; j++)
                    acc[i][j] += qv[i] * (kv[j] + ev[i - j + 3]);
        }

        // exp / masks -> P
        #pragma unroll
        for (int i = 0; i < 4; i++) {
            #pragma unroll
            for (int j = 0; j < 4; j++) {
                int ri = tx * 4 + j;
                float p = __expf(acc[i][j] * 0.125f + Ms[ri]) * Sk[ri];
                Ps[(ty * 4 + i) * 65 + ri] = p;
                rs[i] += p;
            }
        }
        __syncthreads();

        // O += P @ V
        #pragma unroll 4
        for (int rr = 0; rr < BN; rr++) {
            float pv[4], vv[4];
            #pragma unroll
            for (int i = 0; i < 4; i++) pv[i] = Ps[(ty * 4 + i) * 65 + rr];
            #pragma unroll
            for (int j = 0; j < 4; j++) vv[j] = Vs[rr * 64 + tx * 4 + j];
            #pragma unroll
            for (int i = 0; i < 4; i++)
                #pragma unroll
                for (int j = 0; j < 4; j++)
                    acc_o[i][j] += pv[i] * vv[j];
        }
    }

    __syncthreads();
    // rowsum reduction across the 16 tx lanes per li
    #pragma unroll
    for (int i = 0; i < 4; i++) RS[(ty * 4 + i) * 17 + tx] = rs[i];
    __syncthreads();
    if (tid < 64) {
        float s = 1e-8f;
        #pragma unroll
        for (int t = 0; t < 16; t++) s += RS[tid * 17 + t];
        Rsum[tid] = 1.0f / s;
    }
    __syncthreads();

    #pragma unroll
    for (int i = 0; i < 4; i++) {
        int li = ty * 4 + i;
        float inv = Rsum[li];
        #pragma unroll
        for (int j = 0; j < 4; j++) {
            int d = tx * 4 + j;
            out[(size_t)(b * SS + l0 + li) * HIDD + h * DD + d] = acc_o[i][j] * inv;
        }
    }
}

// ---------------------------------------------------------------------------
extern "C" void kernel_launch(void* const* d_in, const int* in_sizes, int n_in,
                              void* d_out, int out_size)
{
    const float* hs    = (const float*)d_in[0];
    const float* amask = (const float*)d_in[1];
    const int*   skim  = (const int*)  d_in[2];
    const float* Wq    = (const float*)d_in[3];
    const float* bq    = (const float*)d_in[4];
    const float* Wk    = (const float*)d_in[5];
    const float* bk    = (const float*)d_in[6];
    const float* Wv    = (const float*)d_in[7];
    const float* bv    = (const float*)d_in[8];
    const float* dist  = (const float*)d_in[9];
    float* out = (float*)d_out;

    dim3 gg(HIDD / GT, (BB * SS) / GT, 3);   // (8, 32, 3)
    qkv_gemm<<<gg, 256>>>(hs, Wq, bq, Wk, bk, Wv, bv);

    size_t smem = (size_t)SMEM_FLOATS * sizeof(float);
    cudaFuncSetAttribute(attn_kernel, cudaFuncAttributeMaxDynamicSharedMemorySize, (int)smem);
    dim3 ga(SS / BM, HH, BB);                // (16, 16, 4)
    attn_kernel<<<ga, 256, smem>>>(amask, skim, dist, out);
}

// round 6
// speedup vs baseline: 2.8354x; 2.8354x over previous
#include <cuda_runtime.h>

#define BB 4
#define SS 1024
#define HIDD 1024
#define HH 16
#define DD 64
#define MAXP 1024

// Scratch for Q,K,V projections: [B*S, H*D] row-major
__device__ float g_q[BB*SS*HIDD];
__device__ float g_k[BB*SS*HIDD];
__device__ float g_v[BB*SS*HIDD];

// ---------------------------------------------------------------------------
// helpers: tf32 convert + m16n8k8 tf32 mma
// ---------------------------------------------------------------------------
__device__ __forceinline__ unsigned f2tf(float x) {
    unsigned r;
    asm("cvt.rna.tf32.f32 %0, %1;" : "=r"(r) : "f"(x));
    return r;
}
__device__ __forceinline__ uint4 cvt4(float4 v) {
    uint4 r;
    r.x = f2tf(v.x); r.y = f2tf(v.y); r.z = f2tf(v.z); r.w = f2tf(v.w);
    return r;
}
__device__ __forceinline__ void mma8(float* c, const unsigned* a, unsigned b0, unsigned b1) {
    asm volatile(
        "mma.sync.aligned.m16n8k8.row.col.f32.tf32.tf32.f32 "
        "{%0,%1,%2,%3}, {%4,%5,%6,%7}, {%8,%9}, {%0,%1,%2,%3};"
        : "+f"(c[0]), "+f"(c[1]), "+f"(c[2]), "+f"(c[3])
        : "r"(a[0]), "r"(a[1]), "r"(a[2]), "r"(a[3]), "r"(b0), "r"(b1));
}

// ---------------------------------------------------------------------------
// QKV GEMM (tf32 tensor): C[4096,1024] = X @ W + bias, tile 128x128, k-step 16
// 8 warps: wr=w>>1 rows 32*wr (2 m16 tiles), wc=w&1 cols 64*wc (8 n8 tiles)
// ---------------------------------------------------------------------------
#define XS_STR 20    // 20 mod 32 = 4  -> A-frag conflict-free
#define WS_STR 136   // 136 mod 32 = 8 -> B-frag conflict-free

__global__ __launch_bounds__(256) void qkv_gemm(
    const float* __restrict__ X,
    const float* __restrict__ Wq, const float* __restrict__ bq,
    const float* __restrict__ Wk, const float* __restrict__ bk,
    const float* __restrict__ Wv, const float* __restrict__ bv)
{
    const float* Wm; const float* bias; float* out;
    if (blockIdx.z == 0)      { Wm = Wq; bias = bq; out = g_q; }
    else if (blockIdx.z == 1) { Wm = Wk; bias = bk; out = g_k; }
    else                      { Wm = Wv; bias = bv; out = g_v; }

    __shared__ unsigned Xs[128 * XS_STR];
    __shared__ unsigned Ws[16 * WS_STR];

    const int tid = threadIdx.x;
    const int lane = tid & 31, w = tid >> 5;
    const int wr = w >> 1, wc = w & 1;
    const int gid = lane >> 2, tin = lane & 3;
    const int m0 = blockIdx.y * 128, n0 = blockIdx.x * 128;

    float c[2][8][4];
    #pragma unroll
    for (int mt = 0; mt < 2; mt++)
        #pragma unroll
        for (int nt = 0; nt < 8; nt++)
            #pragma unroll
            for (int u = 0; u < 4; u++) c[mt][nt][u] = 0.f;

    for (int k0 = 0; k0 < HIDD; k0 += 16) {
        // X tile 128x16 (coalesced float4 along k), tf32 into Xs[m][k]
        #pragma unroll
        for (int r = 0; r < 2; r++) {
            int idx = tid + r * 256;               // 0..511
            int m = idx >> 2, k4 = (idx & 3) * 4;
            float4 v = *reinterpret_cast<const float4*>(
                &X[(size_t)(m0 + m) * HIDD + k0 + k4]);
            *reinterpret_cast<uint4*>(&Xs[m * XS_STR + k4]) = cvt4(v);
        }
        // W tile 16x128 (coalesced float4 along n), tf32 into Ws[k][n]
        #pragma unroll
        for (int r = 0; r < 2; r++) {
            int idx = tid + r * 256;
            int kk = idx >> 5, n4 = (idx & 31) * 4;
            float4 v = *reinterpret_cast<const float4*>(
                &Wm[(size_t)(k0 + kk) * HIDD + n0 + n4]);
            *reinterpret_cast<uint4*>(&Ws[kk * WS_STR + n4]) = cvt4(v);
        }
        __syncthreads();

        #pragma unroll
        for (int ks = 0; ks < 2; ks++) {
            int kb = ks * 8;
            unsigned a[2][4];
            #pragma unroll
            for (int mt = 0; mt < 2; mt++) {
                int mrow = wr * 32 + mt * 16;
                a[mt][0] = Xs[(mrow + gid    ) * XS_STR + kb + tin];
                a[mt][1] = Xs[(mrow + gid + 8) * XS_STR + kb + tin];
                a[mt][2] = Xs[(mrow + gid    ) * XS_STR + kb + tin + 4];
                a[mt][3] = Xs[(mrow + gid + 8) * XS_STR + kb + tin + 4];
            }
            #pragma unroll
            for (int nt = 0; nt < 8; nt++) {
                int nn = wc * 64 + nt * 8;
                unsigned b0 = Ws[(kb + tin    ) * WS_STR + nn + gid];
                unsigned b1 = Ws[(kb + tin + 4) * WS_STR + nn + gid];
                mma8(c[0][nt], a[0], b0, b1);
                mma8(c[1][nt], a[1], b0, b1);
            }
        }
        __syncthreads();
    }

    // epilogue: + bias
    #pragma unroll
    for (int mt = 0; mt < 2; mt++) {
        int r0 = m0 + wr * 32 + mt * 16 + gid;
        #pragma unroll
        for (int nt = 0; nt < 8; nt++) {
            int col = n0 + wc * 64 + nt * 8 + 2 * tin;
            float b0 = bias[col], b1 = bias[col + 1];
            float2* p0 = reinterpret_cast<float2*>(&out[(size_t)r0 * HIDD + col]);
            *p0 = make_float2(c[mt][nt][0] + b0, c[mt][nt][1] + b1);
            float2* p1 = reinterpret_cast<float2*>(&out[(size_t)(r0 + 8) * HIDD + col]);
            *p1 = make_float2(c[mt][nt][2] + b0, c[mt][nt][3] + b1);
        }
    }
}

// ---------------------------------------------------------------------------
// Fused attention (tf32 tensor):
// per (b,h,64-query tile), iterate key tiles of 64:
//   S_all[64,192] = Q @ [K(64) ; E_band(128)]^T        (mma)
//   P[li,ri] = exp((S1+S2[diag])/8 + amask)*skim       (SIMT, in-place tf32)
//   O += P @ V                                          (mma, reg accum)
// normalize by 1/(eps + rowsum) at the end.
// ---------------------------------------------------------------------------
#define QK_STR 68    // 68 mod 32 = 4 -> row-major [row][k] frag conflict-free
#define V_STR  72    // 72 mod 32 = 8 -> [k][n] B-frag conflict-free
#define S_STR  196   // 196 mod 32 = 4 -> P A-frag conflict-free

// word offsets in dynamic smem
#define OFF_Q   0
#define OFF_K   (OFF_Q + 64 * QK_STR)            // 4352
#define OFF_E   (OFF_K + 64 * QK_STR)            // 8704
#define OFF_V   (OFF_E + 128 * QK_STR)           // 17408
#define OFF_S   (OFF_V + 64 * V_STR)             // 22016
#define OFF_MS  (OFF_S + 64 * S_STR)             // 34560
#define OFF_SK  (OFF_MS + 64)
#define OFF_RS  (OFF_SK + 64)
#define OFF_RSUM (OFF_RS + 64 * 5)
#define SMEM_WORDS (OFF_RSUM + 64)               // 35072 words = 140288 B

__global__ __launch_bounds__(256) void attn_kernel(
    const float* __restrict__ amask,   // [B,S]
    const int*   __restrict__ skim,    // [B,S]
    const float* __restrict__ dist,    // [2*MAXP-1, D]
    float*       __restrict__ out)     // [B,S,HID]
{
    extern __shared__ unsigned smw[];
    unsigned* uQ = smw + OFF_Q;
    unsigned* uK = smw + OFF_K;
    unsigned* uE = smw + OFF_E;
    unsigned* uV = smw + OFF_V;
    float* fS   = reinterpret_cast<float*>(smw + OFF_S);
    float* Ms   = reinterpret_cast<float*>(smw + OFF_MS);
    float* Sk   = reinterpret_cast<float*>(smw + OFF_SK);
    float* RS   = reinterpret_cast<float*>(smw + OFF_RS);
    float* Rsum = reinterpret_cast<float*>(smw + OFF_RSUM);

    const int l0 = blockIdx.x * 64;
    const int h  = blockIdx.y;
    const int b  = blockIdx.z;
    const int tid = threadIdx.x;
    const int lane = tid & 31, w = tid >> 5;
    const int wr = w >> 1, wc = w & 1;
    const int gid = lane >> 2, tin = lane & 3;
    const int mrow = 16 * wr;

    const float* Qg = g_q + (size_t)b * SS * HIDD + h * DD;
    const float* Kg = g_k + (size_t)b * SS * HIDD + h * DD;
    const float* Vg = g_v + (size_t)b * SS * HIDD + h * DD;

    // Q tile once (tf32)
    #pragma unroll
    for (int r = 0; r < 4; r++) {
        int idx = tid + r * 256;                 // 0..1023 float4s
        int li = idx >> 4, d4 = (idx & 15) * 4;
        float4 v = *reinterpret_cast<const float4*>(
            &Qg[(size_t)(l0 + li) * HIDD + d4]);
        *reinterpret_cast<uint4*>(&uQ[li * QK_STR + d4]) = cvt4(v);
    }

    const int li_c = tid & 63, cb = tid >> 6;    // combine mapping
    float rs = 0.f;                              // rowsum partial (16 cols)

    float cO[4][4];
    #pragma unroll
    for (int nt = 0; nt < 4; nt++)
        #pragma unroll
        for (int u = 0; u < 4; u++) cO[nt][u] = 0.f;

    for (int r0 = 0; r0 < SS; r0 += 64) {
        __syncthreads();   // prior iter's smem reads complete

        // K, V tiles (tf32)
        #pragma unroll
        for (int r = 0; r < 4; r++) {
            int idx = tid + r * 256;
            int ri = idx >> 4, d4 = (idx & 15) * 4;
            float4 kv = *reinterpret_cast<const float4*>(
                &Kg[(size_t)(r0 + ri) * HIDD + d4]);
            *reinterpret_cast<uint4*>(&uK[ri * QK_STR + d4]) = cvt4(kv);
            float4 vv = *reinterpret_cast<const float4*>(
                &Vg[(size_t)(r0 + ri) * HIDD + d4]);
            *reinterpret_cast<uint4*>(&uV[ri * V_STR + d4]) = cvt4(vv);
        }
        // E band: 128 rows (e=0..127), global row = base+e, only e<=126 used
        int base = l0 - r0 + MAXP - 1 - 63;
        #pragma unroll
        for (int r = 0; r < 8; r++) {
            int idx = tid + r * 256;
            int e = idx >> 4, d4 = (idx & 15) * 4;
            int g = base + e;
            float4 v = make_float4(0.f, 0.f, 0.f, 0.f);
            if (g < 2 * MAXP - 1)
                v = *reinterpret_cast<const float4*>(&dist[(size_t)g * DD + d4]);
            *reinterpret_cast<uint4*>(&uE[e * QK_STR + d4]) = cvt4(v);
        }
        if (tid < 64) {
            Ms[tid] = amask[b * SS + r0 + tid];
            Sk[tid] = (float)skim[b * SS + r0 + tid];
        }
        __syncthreads();

        // ---- S_all = Q @ [K;E]^T : warp = rows 16*wr, cols 96*wc..+95 ----
        float cS[12][4];
        #pragma unroll
        for (int nt = 0; nt < 12; nt++)
            #pragma unroll
            for (int u = 0; u < 4; u++) cS[nt][u] = 0.f;

        #pragma unroll
        for (int ks = 0; ks < 8; ks++) {
            int kb = ks * 8;
            unsigned a[4];
            a[0] = uQ[(mrow + gid    ) * QK_STR + kb + tin];
            a[1] = uQ[(mrow + gid + 8) * QK_STR + kb + tin];
            a[2] = uQ[(mrow + gid    ) * QK_STR + kb + tin + 4];
            a[3] = uQ[(mrow + gid + 8) * QK_STR + kb + tin + 4];
            #pragma unroll
            for (int nt = 0; nt < 12; nt++) {
                int n0 = wc * 96 + nt * 8;
                const unsigned* brow = (n0 < 64)
                    ? &uK[(n0 + gid) * QK_STR]
                    : &uE[(n0 - 64 + gid) * QK_STR];
                mma8(cS[nt], a, brow[kb + tin], brow[kb + tin + 4]);
            }
        }
        // write S to smem
        #pragma unroll
        for (int nt = 0; nt < 12; nt++) {
            int n0 = wc * 96 + nt * 8 + 2 * tin;
            *reinterpret_cast<float2*>(&fS[(mrow + gid) * S_STR + n0]) =
                make_float2(cS[nt][0], cS[nt][1]);
            *reinterpret_cast<float2*>(&fS[(mrow + gid + 8) * S_STR + n0]) =
                make_float2(cS[nt][2], cS[nt][3]);
        }
        __syncthreads();

        // ---- combine + exp -> P (in place, tf32, cols 0..63) ----
        {
            float* Srow = &fS[li_c * S_STR];
            #pragma unroll
            for (int jj = 0; jj < 4; jj++) {
                int j = cb * 16 + jj * 4;
                float4 s1 = *reinterpret_cast<const float4*>(&Srow[j]);
                float s1a[4] = {s1.x, s1.y, s1.z, s1.w};
                float pv[4];
                #pragma unroll
                for (int u = 0; u < 4; u++) {
                    int ri = j + u;
                    float s2 = Srow[64 + li_c - ri + 63];
                    float p = __expf((s1a[u] + s2) * 0.125f + Ms[ri]) * Sk[ri];
                    rs += p;
                    pv[u] = __uint_as_float(f2tf(p));
                }
                *reinterpret_cast<float4*>(&Srow[j]) =
                    make_float4(pv[0], pv[1], pv[2], pv[3]);
            }
        }
        __syncthreads();

        // ---- O += P @ V : warp = rows 16*wr, cols 32*wc..+31 ----
        const unsigned* Pb = reinterpret_cast<const unsigned*>(fS);
        #pragma unroll
        for (int ks = 0; ks < 8; ks++) {
            int kb = ks * 8;
            unsigned a[4];
            a[0] = Pb[(mrow + gid    ) * S_STR + kb + tin];
            a[1] = Pb[(mrow + gid + 8) * S_STR + kb + tin];
            a[2] = Pb[(mrow + gid    ) * S_STR + kb + tin + 4];
            a[3] = Pb[(mrow + gid + 8) * S_STR + kb + tin + 4];
            #pragma unroll
            for (int nt = 0; nt < 4; nt++) {
                int n0 = wc * 32 + nt * 8;
                unsigned b0 = uV[(kb + tin    ) * V_STR + n0 + gid];
                unsigned b1 = uV[(kb + tin + 4) * V_STR + n0 + gid];
                mma8(cO[nt], a, b0, b1);
            }
        }
    }

    __syncthreads();
    RS[li_c * 5 + cb] = rs;
    __syncthreads();
    if (tid < 64) {
        float s = 1e-8f + RS[tid * 5] + RS[tid * 5 + 1] + RS[tid * 5 + 2] + RS[tid * 5 + 3];
        Rsum[tid] = 1.0f / s;
    }
    __syncthreads();

    // write O
    float inv0 = Rsum[mrow + gid], inv1 = Rsum[mrow + gid + 8];
    #pragma unroll
    for (int nt = 0; nt < 4; nt++) {
        int col = h * DD + wc * 32 + nt * 8 + 2 * tin;
        size_t g0 = (size_t)(b * SS + l0 + mrow + gid) * HIDD + col;
        size_t g1 = (size_t)(b * SS + l0 + mrow + gid + 8) * HIDD + col;
        *reinterpret_cast<float2*>(&out[g0]) =
            make_float2(cO[nt][0] * inv0, cO[nt][1] * inv0);
        *reinterpret_cast<float2*>(&out[g1]) =
            make_float2(cO[nt][2] * inv1, cO[nt][3] * inv1);
    }
}

// ---------------------------------------------------------------------------
extern "C" void kernel_launch(void* const* d_in, const int* in_sizes, int n_in,
                              void* d_out, int out_size)
{
    const float* hs    = (const float*)d_in[0];
    const float* amask = (const float*)d_in[1];
    const int*   skim  = (const int*)  d_in[2];
    const float* Wq    = (const float*)d_in[3];
    const float* bq    = (const float*)d_in[4];
    const float* Wk    = (const float*)d_in[5];
    const float* bk    = (const float*)d_in[6];
    const float* Wv    = (const float*)d_in[7];
    const float* bv    = (const float*)d_in[8];
    const float* dist  = (const float*)d_in[9];
    float* out = (float*)d_out;

    dim3 gg(HIDD / 128, (BB * SS) / 128, 3);   // (8, 32, 3)
    qkv_gemm<<<gg, 256>>>(hs, Wq, bq, Wk, bk, Wv, bv);

    size_t smem = (size_t)SMEM_WORDS * sizeof(unsigned);
    cudaFuncSetAttribute(attn_kernel, cudaFuncAttributeMaxDynamicSharedMemorySize, (int)smem);
    dim3 ga(SS / 64, HH, BB);                  // (16, 16, 4)
    attn_kernel<<<ga, 256, smem>>>(amask, skim, dist, out);
}